// round 15
// baseline (speedup 1.0000x reference)
#include <cuda_runtime.h>
#include <cuda_fp16.h>
#include <cuda_bf16.h>

// Fixed problem shapes:
//   tex (8,16,512,512) f32, iuv (8,3,512,512) i32, lut (24,256,256,2) f32,
//   tex_res = 512 (1-element i32 device scalar), out (8,16,512,512) f32.
#define BB 8
#define CC 16
#define RR 512
#define RR2 (RR * RR)        // 2^18
#define HW  (512 * 512)      // 2^18
#define LOG2_RR2 18
#define LOG2_HW  18

#define TR_BLOCKS  ((BB * RR2) / 256)    // 8192: transpose role
#define IDX_BLOCKS ((BB * HW)  / 256)    // 8192: index-precompute role

// FULL transposed texture in fp16: [b][pixel][channel] = 64 MiB, L2-resident.
__device__ __align__(256) __half g_scratch[(size_t)BB * RR2 * CC];
// Per-pixel texel index (v_I*512 + u_I), or -1 if masked. 8 MB.
__device__ int g_idx[(size_t)BB * HW];

// 256-bit global load (sm_100+): one LDG.E.256.
__device__ __forceinline__ void ldg256(const void* p, unsigned int w[8]) {
    asm("ld.global.v8.u32 {%0,%1,%2,%3,%4,%5,%6,%7}, [%8];"
        : "=r"(w[0]), "=r"(w[1]), "=r"(w[2]), "=r"(w[3]),
          "=r"(w[4]), "=r"(w[5]), "=r"(w[6]), "=r"(w[7])
        : "l"(p));
}

// ---------------------------------------------------------------------------
// Fused prep, two independent producer roles (R14-proven pattern):
//  blocks [0, TR_BLOCKS):      transpose tex -> fp16 scratch (R11 body)
//  blocks [TR_BLOCKS, +IDX):   per-pixel index precompute from iuv + lut
// ---------------------------------------------------------------------------
__global__ void __launch_bounds__(256) prep_kernel(
    const float* __restrict__ tex,
    const int*   __restrict__ iuv,
    const float* __restrict__ lut,
    const int*   __restrict__ tex_res_ptr)
{
    if ((int)blockIdx.x < TR_BLOCKS) {
        // -------- transpose: 4 channels x 4 pixels per thread --------------
        int idx = blockIdx.x * 256 + threadIdx.x;       // [0, BB*RR2)
        int b  = idx >> LOG2_RR2;                       // batch
        int t  = idx & (RR2 - 1);
        int c4 = t & 3;                                 // channel group 0..3
        int p4 = (t >> 2) * 4;                          // first of 4 pixels

        const float* src = tex + ((size_t)b * CC + (size_t)c4 * 4) * RR2 + p4;
        float4 f0 = __ldcs(reinterpret_cast<const float4*>(src + 0 * RR2));
        float4 f1 = __ldcs(reinterpret_cast<const float4*>(src + 1 * RR2));
        float4 f2 = __ldcs(reinterpret_cast<const float4*>(src + 2 * RR2));
        float4 f3 = __ldcs(reinterpret_cast<const float4*>(src + 3 * RR2));

        __half* dst = g_scratch + ((size_t)b * RR2 + p4) * CC + (size_t)c4 * 4;
        const float* a0 = reinterpret_cast<const float*>(&f0);
        const float* a1 = reinterpret_cast<const float*>(&f1);
        const float* a2 = reinterpret_cast<const float*>(&f2);
        const float* a3 = reinterpret_cast<const float*>(&f3);
        #pragma unroll
        for (int j = 0; j < 4; j++) {                   // pixel within quad
            __half2 h0 = __floats2half2_rn(a0[j], a1[j]);
            __half2 h1 = __floats2half2_rn(a2[j], a3[j]);
            uint2 w;
            w.x = *reinterpret_cast<const unsigned int*>(&h0);
            w.y = *reinterpret_cast<const unsigned int*>(&h1);
            *reinterpret_cast<uint2*>(dst + (size_t)j * CC) = w;
        }
    } else {
        // -------- index precompute: 1 pixel per thread ---------------------
        int idx = (blockIdx.x - TR_BLOCKS) * 256 + threadIdx.x; // [0, BB*HW)
        int pix = idx & (HW - 1);
        int b   = idx >> LOG2_HW;

        const int* iuvb = iuv + (size_t)b * 3 * HW + pix;
        int part = __ldcs(iuvb);

        int vu = -1;
        if (part > 0) {
            // Exact shortcut: round(clip(n/255)*255) == n for n in [0,255].
            int ui = min(max(__ldcs(iuvb + 1 * HW), 0), 255);
            int vi = min(max(__ldcs(iuvb + 2 * HW), 0), 255);
            int i  = min(max(part - 1, 0), 23);

            // Identical float math to the reference (bit-identical indices).
            float2 uv = __ldg(reinterpret_cast<const float2*>(lut)
                              + ((size_t)i * 256 + vi) * 256 + ui);
            float resm1 = (float)(__ldg(tex_res_ptr) - 1);
            int u_I = min(max(__float2int_rn(uv.x * resm1), 0), RR - 1);
            int v_I = min(max(__float2int_rn((1.0f - uv.y) * resm1), 0), RR - 1);
            vu = v_I * RR + u_I;
        }
        g_idx[idx] = vu;    // coalesced 4B store
    }
}

// ---------------------------------------------------------------------------
// Gather: one thread per (b, pixel), ONE launch over all batches.
// Minimal chain: coalesced idx load -> LDG.256 scratch gather -> 16 stores.
// ~49 L1 wavefronts/warp vs ~80 before.
// ---------------------------------------------------------------------------
__global__ void __launch_bounds__(256) densepose_kernel(
    float* __restrict__ out)
{
    int idx = blockIdx.x * blockDim.x + threadIdx.x;   // [0, BB*HW)
    int pix = idx & (HW - 1);
    int b   = idx >> LOG2_HW;

    int vu = __ldcs(g_idx + idx);

    float r[16];
    #pragma unroll
    for (int c = 0; c < 16; c++) r[c] = 0.f;

    if (vu >= 0) {
        unsigned int w[8];
        ldg256(g_scratch + ((size_t)b * RR2 + (size_t)vu) * 16, w);
        #pragma unroll
        for (int j = 0; j < 8; j++) {
            __half2 h = *reinterpret_cast<const __half2*>(&w[j]);
            float2 f = __half22float2(h);
            r[2 * j]     = f.x;
            r[2 * j + 1] = f.y;
        }
    }

    // Output (B,C,H,W): 16 fully-coalesced scalar stores, write-through.
    float* o = out + (size_t)b * CC * HW + pix;
    #pragma unroll
    for (int c = 0; c < 16; c++)
        __stwt(o + (size_t)c * HW, r[c]);
}

extern "C" void kernel_launch(void* const* d_in, const int* in_sizes, int n_in,
                              void* d_out, int out_size)
{
    const float* tex     = (const float*)d_in[0];
    const int*   iuv     = (const int*)  d_in[1];
    const float* lut     = (const float*)d_in[2];
    const int*   tex_res = (const int*)  d_in[3];
    float* out = (float*)d_out;

    prep_kernel<<<TR_BLOCKS + IDX_BLOCKS, 256>>>(tex, iuv, lut, tex_res);
    densepose_kernel<<<(BB * HW) / 256, 256>>>(out);
}

// round 16
// speedup vs baseline: 1.0598x; 1.0598x over previous
#include <cuda_runtime.h>
#include <cuda_fp16.h>
#include <cuda_bf16.h>

// Fixed problem shapes:
//   tex (8,16,512,512) f32, iuv (8,3,512,512) i32, lut (24,256,256,2) f32,
//   tex_res = 512 (1-element i32 device scalar), out (8,16,512,512) f32.
#define BB 8
#define CC 16
#define RR 512
#define RR2 (RR * RR)        // 2^18
#define HW  (512 * 512)      // 2^18
#define LOG2_RR2 18
#define LOG2_HW  18
#define NLUT (24 * 256 * 256)
#define PACK_BLOCKS ((NLUT / 4) / 256)     // 1536: one thread = 4 entries
#define TR_BLOCKS   ((BB * RR2) / 256)     // 8192

// FULL transposed texture in fp16: [b][pixel][channel] = 64 MiB, L2-resident.
__device__ __align__(256) __half g_scratch[(size_t)BB * RR2 * CC];
// Pre-packed texel indices: v_I*512 + u_I per (part, vi, ui). 6 MiB.
__device__ __align__(16) int g_packed[NLUT];

// 256-bit global load (sm_100+): one LDG.E.256.
__device__ __forceinline__ void ldg256(const void* p, unsigned int w[8]) {
    asm("ld.global.v8.u32 {%0,%1,%2,%3,%4,%5,%6,%7}, [%8];"
        : "=r"(w[0]), "=r"(w[1]), "=r"(w[2]), "=r"(w[3]),
          "=r"(w[4]), "=r"(w[5]), "=r"(w[6]), "=r"(w[7])
        : "l"(p));
}

// ---------------------------------------------------------------------------
// Fused prep (R14-proven): blocks [0, PACK_BLOCKS) pack the LUT (4 entries
// per thread); remaining blocks transpose tex -> fp16 scratch (R11 body).
// ---------------------------------------------------------------------------
__global__ void __launch_bounds__(256) prep_kernel(
    const float* __restrict__ tex,
    const float* __restrict__ lut,
    const int*   __restrict__ tex_res_ptr)
{
    if ((int)blockIdx.x < PACK_BLOCKS) {
        // -------- pack LUT: 4 entries per thread ---------------------------
        int e4 = (blockIdx.x * 256 + threadIdx.x) * 4;   // first entry
        float4 q0 = __ldcs(reinterpret_cast<const float4*>(lut) + (e4 >> 1));
        float4 q1 = __ldcs(reinterpret_cast<const float4*>(lut) + (e4 >> 1) + 1);
        float resm1 = (float)(__ldg(tex_res_ptr) - 1);

        // Identical float math to the reference (bit-identical indices).
        int4 o;
        {
            int u = min(max(__float2int_rn(q0.x * resm1), 0), RR - 1);
            int v = min(max(__float2int_rn((1.0f - q0.y) * resm1), 0), RR - 1);
            o.x = v * RR + u;
        }
        {
            int u = min(max(__float2int_rn(q0.z * resm1), 0), RR - 1);
            int v = min(max(__float2int_rn((1.0f - q0.w) * resm1), 0), RR - 1);
            o.y = v * RR + u;
        }
        {
            int u = min(max(__float2int_rn(q1.x * resm1), 0), RR - 1);
            int v = min(max(__float2int_rn((1.0f - q1.y) * resm1), 0), RR - 1);
            o.z = v * RR + u;
        }
        {
            int u = min(max(__float2int_rn(q1.z * resm1), 0), RR - 1);
            int v = min(max(__float2int_rn((1.0f - q1.w) * resm1), 0), RR - 1);
            o.w = v * RR + u;
        }
        *reinterpret_cast<int4*>(g_packed + e4) = o;
    } else {
        // -------- transpose: 4 channels x 4 pixels per thread --------------
        int idx = (blockIdx.x - PACK_BLOCKS) * 256 + threadIdx.x;
        int b  = idx >> LOG2_RR2;                       // batch
        int t  = idx & (RR2 - 1);
        int c4 = t & 3;                                 // channel group 0..3
        int p4 = (t >> 2) * 4;                          // first of 4 pixels

        const float* src = tex + ((size_t)b * CC + (size_t)c4 * 4) * RR2 + p4;
        float4 f0 = __ldcs(reinterpret_cast<const float4*>(src + 0 * RR2));
        float4 f1 = __ldcs(reinterpret_cast<const float4*>(src + 1 * RR2));
        float4 f2 = __ldcs(reinterpret_cast<const float4*>(src + 2 * RR2));
        float4 f3 = __ldcs(reinterpret_cast<const float4*>(src + 3 * RR2));

        __half* dst = g_scratch + ((size_t)b * RR2 + p4) * CC + (size_t)c4 * 4;
        const float* a0 = reinterpret_cast<const float*>(&f0);
        const float* a1 = reinterpret_cast<const float*>(&f1);
        const float* a2 = reinterpret_cast<const float*>(&f2);
        const float* a3 = reinterpret_cast<const float*>(&f3);
        #pragma unroll
        for (int j = 0; j < 4; j++) {                   // pixel within quad
            __half2 h0 = __floats2half2_rn(a0[j], a1[j]);
            __half2 h1 = __floats2half2_rn(a2[j], a3[j]);
            uint2 w;
            w.x = *reinterpret_cast<const unsigned int*>(&h0);
            w.y = *reinterpret_cast<const unsigned int*>(&h1);
            *reinterpret_cast<uint2*>(dst + (size_t)j * CC) = w;
        }
    }
}

// ---------------------------------------------------------------------------
// Gather: one thread per (b, pixel), ONE launch, fully BRANCHLESS.
// part/u8/v8 issue in parallel (no branch gating them), then packed idx,
// then LDG.256 scratch gather; mask to zero at the end. Chain: 3 levels
// with front-batched leading loads (vs 4 effective levels when u8/v8 sat
// behind the part branch).
// ---------------------------------------------------------------------------
__global__ void __launch_bounds__(256) densepose_kernel(
    const int*   __restrict__ iuv,
    float*       __restrict__ out)
{
    int idx = blockIdx.x * blockDim.x + threadIdx.x;   // [0, BB*HW)
    int pix = idx & (HW - 1);
    int b   = idx >> LOG2_HW;

    // Front-batched, always-in-bounds loads (3 parallel L2/DRAM requests).
    const int* iuvb = iuv + (size_t)b * 3 * HW + pix;
    int part = __ldcs(iuvb);
    int u8   = __ldcs(iuvb + 1 * HW);
    int v8   = __ldcs(iuvb + 2 * HW);

    // Exact shortcut: round(clip(n/255)*255) == n for n in [0,255].
    int ui = min(max(u8, 0), 255);
    int vi = min(max(v8, 0), 255);
    int i  = min(max(part - 1, 0), 23);

    // Always-valid packed index (clamped) -> unconditional loads.
    int vu = __ldg(g_packed + ((size_t)i * 256 + vi) * 256 + ui);

    unsigned int w[8];
    ldg256(g_scratch + ((size_t)b * RR2 + (size_t)vu) * 16, w);

    float mask = (part > 0) ? 1.0f : 0.0f;
    float r[16];
    #pragma unroll
    for (int j = 0; j < 8; j++) {
        __half2 h = *reinterpret_cast<const __half2*>(&w[j]);
        float2 f = __half22float2(h);
        r[2 * j]     = f.x * mask;
        r[2 * j + 1] = f.y * mask;
    }

    // Output (B,C,H,W): 16 fully-coalesced scalar stores, write-through.
    float* o = out + (size_t)b * CC * HW + pix;
    #pragma unroll
    for (int c = 0; c < 16; c++)
        __stwt(o + (size_t)c * HW, r[c]);
}

extern "C" void kernel_launch(void* const* d_in, const int* in_sizes, int n_in,
                              void* d_out, int out_size)
{
    const float* tex     = (const float*)d_in[0];
    const int*   iuv     = (const int*)  d_in[1];
    const float* lut     = (const float*)d_in[2];
    const int*   tex_res = (const int*)  d_in[3];
    float* out = (float*)d_out;

    prep_kernel<<<PACK_BLOCKS + TR_BLOCKS, 256>>>(tex, lut, tex_res);
    densepose_kernel<<<(BB * HW) / 256, 256>>>(iuv, out);
}

// round 17
// speedup vs baseline: 1.0767x; 1.0159x over previous
#include <cuda_runtime.h>
#include <cuda_fp16.h>
#include <cuda_bf16.h>

// Fixed problem shapes:
//   tex (8,16,512,512) f32, iuv (8,3,512,512) i32, lut (24,256,256,2) f32,
//   tex_res = 512 (1-element i32 device scalar), out (8,16,512,512) f32.
#define BB 8
#define CC 16
#define RR 512
#define RR2 (RR * RR)        // 2^18
#define HW  (512 * 512)      // 2^18
#define LOG2_RR2 18
#define LOG2_HW  18
#define NLUT (24 * 256 * 256)
#define PACK_BLOCKS ((NLUT / 4) / 256)     // 1536: one thread = 4 entries
#define TR_BLOCKS   ((BB * RR2) / 256)     // 8192

// FULL transposed texture in fp16: [b][pixel][channel] = 64 MiB, L2-resident.
__device__ __align__(256) __half g_scratch[(size_t)BB * RR2 * CC];
// Pre-packed texel indices: v_I*512 + u_I per (part, vi, ui). 6 MiB.
__device__ __align__(16) int g_packed[NLUT];

// 256-bit global load (sm_100+): one LDG.E.256.
__device__ __forceinline__ void ldg256(const void* p, unsigned int w[8]) {
    asm("ld.global.v8.u32 {%0,%1,%2,%3,%4,%5,%6,%7}, [%8];"
        : "=r"(w[0]), "=r"(w[1]), "=r"(w[2]), "=r"(w[3]),
          "=r"(w[4]), "=r"(w[5]), "=r"(w[6]), "=r"(w[7])
        : "l"(p));
}

// ---------------------------------------------------------------------------
// Fused prep (R14-proven): blocks [0, PACK_BLOCKS) pack the LUT (4 entries
// per thread); remaining blocks transpose tex -> fp16 scratch (R11 body).
// Implicit end-of-kernel PDL trigger: all writes visible to the dependent
// gather at its cudaGridDependencySynchronize().
// ---------------------------------------------------------------------------
__global__ void __launch_bounds__(256) prep_kernel(
    const float* __restrict__ tex,
    const float* __restrict__ lut,
    const int*   __restrict__ tex_res_ptr)
{
    if ((int)blockIdx.x < PACK_BLOCKS) {
        // -------- pack LUT: 4 entries per thread ---------------------------
        int e4 = (blockIdx.x * 256 + threadIdx.x) * 4;   // first entry
        float4 q0 = __ldcs(reinterpret_cast<const float4*>(lut) + (e4 >> 1));
        float4 q1 = __ldcs(reinterpret_cast<const float4*>(lut) + (e4 >> 1) + 1);
        float resm1 = (float)(__ldg(tex_res_ptr) - 1);

        // Identical float math to the reference (bit-identical indices).
        int4 o;
        {
            int u = min(max(__float2int_rn(q0.x * resm1), 0), RR - 1);
            int v = min(max(__float2int_rn((1.0f - q0.y) * resm1), 0), RR - 1);
            o.x = v * RR + u;
        }
        {
            int u = min(max(__float2int_rn(q0.z * resm1), 0), RR - 1);
            int v = min(max(__float2int_rn((1.0f - q0.w) * resm1), 0), RR - 1);
            o.y = v * RR + u;
        }
        {
            int u = min(max(__float2int_rn(q1.x * resm1), 0), RR - 1);
            int v = min(max(__float2int_rn((1.0f - q1.y) * resm1), 0), RR - 1);
            o.z = v * RR + u;
        }
        {
            int u = min(max(__float2int_rn(q1.z * resm1), 0), RR - 1);
            int v = min(max(__float2int_rn((1.0f - q1.w) * resm1), 0), RR - 1);
            o.w = v * RR + u;
        }
        *reinterpret_cast<int4*>(g_packed + e4) = o;
    } else {
        // -------- transpose: 4 channels x 4 pixels per thread --------------
        int idx = (blockIdx.x - PACK_BLOCKS) * 256 + threadIdx.x;
        int b  = idx >> LOG2_RR2;                       // batch
        int t  = idx & (RR2 - 1);
        int c4 = t & 3;                                 // channel group 0..3
        int p4 = (t >> 2) * 4;                          // first of 4 pixels

        const float* src = tex + ((size_t)b * CC + (size_t)c4 * 4) * RR2 + p4;
        float4 f0 = __ldcs(reinterpret_cast<const float4*>(src + 0 * RR2));
        float4 f1 = __ldcs(reinterpret_cast<const float4*>(src + 1 * RR2));
        float4 f2 = __ldcs(reinterpret_cast<const float4*>(src + 2 * RR2));
        float4 f3 = __ldcs(reinterpret_cast<const float4*>(src + 3 * RR2));

        __half* dst = g_scratch + ((size_t)b * RR2 + p4) * CC + (size_t)c4 * 4;
        const float* a0 = reinterpret_cast<const float*>(&f0);
        const float* a1 = reinterpret_cast<const float*>(&f1);
        const float* a2 = reinterpret_cast<const float*>(&f2);
        const float* a3 = reinterpret_cast<const float*>(&f3);
        #pragma unroll
        for (int j = 0; j < 4; j++) {                   // pixel within quad
            __half2 h0 = __floats2half2_rn(a0[j], a1[j]);
            __half2 h1 = __floats2half2_rn(a2[j], a3[j]);
            uint2 w;
            w.x = *reinterpret_cast<const unsigned int*>(&h0);
            w.y = *reinterpret_cast<const unsigned int*>(&h1);
            *reinterpret_cast<uint2*>(dst + (size_t)j * CC) = w;
        }
    }
}

// ---------------------------------------------------------------------------
// Gather (PDL secondary): blocks may launch while prep's tail drains.
// Phase A (independent of prep): 3 iuv loads issue immediately.
// cudaGridDependencySynchronize() -> then packed + scratch (prep outputs).
// Body otherwise bit-identical to the R16 winner.
// ---------------------------------------------------------------------------
__global__ void __launch_bounds__(256) densepose_kernel(
    const int*   __restrict__ iuv,
    float*       __restrict__ out)
{
    int idx = blockIdx.x * blockDim.x + threadIdx.x;   // [0, BB*HW)
    int pix = idx & (HW - 1);
    int b   = idx >> LOG2_HW;

    // Phase A: input-only loads, legal before the prep dependency resolves.
    const int* iuvb = iuv + (size_t)b * 3 * HW + pix;
    int part = __ldcs(iuvb);
    int u8   = __ldcs(iuvb + 1 * HW);
    int v8   = __ldcs(iuvb + 2 * HW);

    // Exact shortcut: round(clip(n/255)*255) == n for n in [0,255].
    int ui = min(max(u8, 0), 255);
    int vi = min(max(v8, 0), 255);
    int i  = min(max(part - 1, 0), 23);

    // Wait for prep's scratch + packed writes (no-op if launched w/o PDL).
    cudaGridDependencySynchronize();

    int vu = __ldg(g_packed + ((size_t)i * 256 + vi) * 256 + ui);

    unsigned int w[8];
    ldg256(g_scratch + ((size_t)b * RR2 + (size_t)vu) * 16, w);

    float mask = (part > 0) ? 1.0f : 0.0f;
    float r[16];
    #pragma unroll
    for (int j = 0; j < 8; j++) {
        __half2 h = *reinterpret_cast<const __half2*>(&w[j]);
        float2 f = __half22float2(h);
        r[2 * j]     = f.x * mask;
        r[2 * j + 1] = f.y * mask;
    }

    // Output (B,C,H,W): 16 fully-coalesced scalar stores, write-through.
    float* o = out + (size_t)b * CC * HW + pix;
    #pragma unroll
    for (int c = 0; c < 16; c++)
        __stwt(o + (size_t)c * HW, r[c]);
}

extern "C" void kernel_launch(void* const* d_in, const int* in_sizes, int n_in,
                              void* d_out, int out_size)
{
    const float* tex     = (const float*)d_in[0];
    const int*   iuv     = (const int*)  d_in[1];
    const float* lut     = (const float*)d_in[2];
    const int*   tex_res = (const int*)  d_in[3];
    float* out = (float*)d_out;

    prep_kernel<<<PACK_BLOCKS + TR_BLOCKS, 256>>>(tex, lut, tex_res);

    // PDL launch: gather may start while prep drains; it synchronizes on
    // prep's completion before touching g_packed / g_scratch.
    cudaLaunchConfig_t cfg = {};
    cfg.gridDim  = dim3((BB * HW) / 256);
    cfg.blockDim = dim3(256);
    cudaLaunchAttribute attr[1];
    attr[0].id = cudaLaunchAttributeProgrammaticStreamSerialization;
    attr[0].val.programmaticStreamSerializationAllowed = 1;
    cfg.attrs = attr;
    cfg.numAttrs = 1;
    cudaError_t e = cudaLaunchKernelEx(&cfg, densepose_kernel, iuv, out);
    if (e != cudaSuccess) {
        // Fallback: plain serialized launch (sync inside becomes a no-op).
        densepose_kernel<<<(BB * HW) / 256, 256>>>(iuv, out);
    }
}